// round 16
// baseline (speedup 1.0000x reference)
#include <cuda_runtime.h>
#include <math.h>

#define BSZ   4
#define NN    2048
#define HH    2
#define FD    768
#define NEG   0.2f

// ---------------------------------------------------------------------------
// Device scratch (static allocation — no cudaMalloc allowed)
// ---------------------------------------------------------------------------
__device__ float g_hprime[(size_t)BSZ * HH * NN * FD];   // [b,h,n,f]  50.3 MB
__device__ float g_P     [(size_t)BSZ * HH * NN * NN];   // [b,h,i,j] 134.2 MB
__device__ float g_src   [BSZ * HH * NN];
__device__ float g_dst   [BSZ * HH * NN];

// ---------------------------------------------------------------------------
// Tiled SGEMM: 64x64 C tile, BK=16, 256 threads, 4x4 per thread.
// FROM_P=false :  h_prime[bh] = h[b] (2048x768) @ w[hd] (768x768)
// FROM_P=true  :  out[bh]     = P[bh] (2048x2048) @ h_prime[bh] (2048x768) + bias
// ---------------------------------------------------------------------------
template <bool FROM_P>
__global__ __launch_bounds__(256) void gemm64(const float* __restrict__ Xglob,
                                              const float* __restrict__ Wglob,
                                              float* __restrict__ OutGlob,
                                              const float* __restrict__ bias,
                                              int K)
{
    const int bh = blockIdx.z;

    const float* A;
    const float* B;
    float*       C;
    int lda;

    if (FROM_P) {
        A   = g_P      + (size_t)bh * NN * NN;   lda = NN;
        B   = g_hprime + (size_t)bh * NN * FD;
        C   = OutGlob  + (size_t)bh * NN * FD;
    } else {
        A   = Xglob    + (size_t)(bh / HH) * NN * FD;  lda = FD;
        B   = Wglob    + (size_t)(bh % HH) * FD * FD;
        C   = g_hprime + (size_t)bh * NN * FD;
    }
    const int ldb = FD;

    const int m0 = blockIdx.x * 64;
    const int n0 = blockIdx.y * 64;

    __shared__ float As[16][64];   // A transposed: As[k][m]
    __shared__ float Bs[16][64];

    const int tid = threadIdx.x;
    const int tx  = tid & 15;      // 0..15  -> 4 cols each
    const int ty  = tid >> 4;      // 0..15  -> 4 rows each

    // load indices
    const int ar = tid >> 2;             // 0..63 (row within A tile)
    const int ac = (tid & 3) * 4;        // 0,4,8,12 (k within A tile)
    const int br = tid >> 4;             // 0..15 (k within B tile)
    const int bc = (tid & 15) * 4;       // 0..60 (col within B tile)

    float acc[4][4] = {};

    for (int k0 = 0; k0 < K; k0 += 16) {
        float4 a4 = *reinterpret_cast<const float4*>(
            A + (size_t)(m0 + ar) * lda + k0 + ac);
        As[ac + 0][ar] = a4.x;
        As[ac + 1][ar] = a4.y;
        As[ac + 2][ar] = a4.z;
        As[ac + 3][ar] = a4.w;

        *reinterpret_cast<float4*>(&Bs[br][bc]) =
            *reinterpret_cast<const float4*>(B + (size_t)(k0 + br) * ldb + n0 + bc);

        __syncthreads();

#pragma unroll
        for (int kk = 0; kk < 16; kk++) {
            float4 av = *reinterpret_cast<const float4*>(&As[kk][ty * 4]);
            float4 bv = *reinterpret_cast<const float4*>(&Bs[kk][tx * 4]);
            float a[4] = {av.x, av.y, av.z, av.w};
            float b[4] = {bv.x, bv.y, bv.z, bv.w};
#pragma unroll
            for (int i = 0; i < 4; i++)
#pragma unroll
                for (int j = 0; j < 4; j++)
                    acc[i][j] = fmaf(a[i], b[j], acc[i][j]);
        }
        __syncthreads();
    }

#pragma unroll
    for (int i = 0; i < 4; i++) {
        const int row = m0 + ty * 4 + i;
        const int col = n0 + tx * 4;
        float4 o;
        o.x = acc[i][0]; o.y = acc[i][1]; o.z = acc[i][2]; o.w = acc[i][3];
        if (FROM_P) {
            o.x += bias[col + 0];
            o.y += bias[col + 1];
            o.z += bias[col + 2];
            o.w += bias[col + 3];
        }
        *reinterpret_cast<float4*>(C + (size_t)row * FD + col) = o;
    }
}

// ---------------------------------------------------------------------------
// attn_src / attn_dst : per row, dot(tanh(h_prime_row), a_src[h]) etc.
// One 256-thread block per row (grid = BS*H*N = 16384).
// ---------------------------------------------------------------------------
__global__ __launch_bounds__(256) void attn_vec_kernel(const float* __restrict__ a_src,
                                                       const float* __restrict__ a_dst)
{
    const int row = blockIdx.x;                 // bh*NN + i
    const int hd  = (row / NN) % HH;
    const float* hp = g_hprime + (size_t)row * FD;

    const int t = threadIdx.x;
    float s = 0.f, d = 0.f;
#pragma unroll
    for (int k = 0; k < FD / 256; k++) {
        const int f = t + k * 256;
        const float v = tanhf(hp[f]);
        s = fmaf(v, a_src[hd * FD + f], s);
        d = fmaf(v, a_dst[hd * FD + f], d);
    }

    __shared__ float rs[256], rd[256];
    rs[t] = s; rd[t] = d;
    __syncthreads();
    for (int off = 128; off > 0; off >>= 1) {
        if (t < off) { rs[t] += rs[t + off]; rd[t] += rd[t + off]; }
        __syncthreads();
    }
    if (t == 0) {
        g_src[row] = rs[0];
        g_dst[row] = rd[0];
    }
}

// ---------------------------------------------------------------------------
// Softmax over j for each (b,h,i) row; writes normalized P to global scratch.
// score = leaky_relu(src_i + dst_j), masked by (adj[b,i,j] || i==j).
// adj arrives as int32 (harness converts JAX bool -> int32).
// One 256-thread block per row.
// ---------------------------------------------------------------------------
__global__ __launch_bounds__(256) void softmax_p_kernel(const int* __restrict__ adj)
{
    const int row = blockIdx.x;                 // bh*NN + i
    const int bh  = row / NN;
    const int i   = row % NN;
    const int b   = bh / HH;

    const int* arow = adj + (size_t)b * NN * NN + (size_t)i * NN;
    float* prow = g_P + (size_t)bh * NN * NN + (size_t)i * NN;
    const float srci = g_src[row];
    const float* dstp = g_dst + (size_t)bh * NN;

    __shared__ float sc[NN];
    __shared__ float red[256];

    const int t = threadIdx.x;

    float lmax = -INFINITY;
#pragma unroll
    for (int k = 0; k < NN / 256; k++) {
        const int j = t + k * 256;
        float s = srci + dstp[j];
        s = (s >= 0.f) ? s : NEG * s;           // leaky_relu BEFORE mask (ref semantics)
        const bool keep = (arow[j] != 0) || (j == i);
        s = keep ? s : -INFINITY;
        sc[j] = s;
        lmax = fmaxf(lmax, s);
    }

    red[t] = lmax;
    __syncthreads();
    for (int off = 128; off > 0; off >>= 1) {
        if (t < off) red[t] = fmaxf(red[t], red[t + off]);
        __syncthreads();
    }
    const float rowmax = red[0];
    __syncthreads();

    float lsum = 0.f;
#pragma unroll
    for (int k = 0; k < NN / 256; k++) {
        const int j = t + k * 256;
        const float e = expf(sc[j] - rowmax);   // exp(-inf)=0 for masked
        sc[j] = e;
        lsum += e;
    }
    red[t] = lsum;
    __syncthreads();
    for (int off = 128; off > 0; off >>= 1) {
        if (t < off) red[t] += red[t + off];
        __syncthreads();
    }
    const float inv = 1.f / red[0];
    __syncthreads();

#pragma unroll
    for (int k = 0; k < NN / 256; k++) {
        const int j = t + k * 256;
        prow[j] = sc[j] * inv;
    }
}

// ---------------------------------------------------------------------------
// Launch
// ---------------------------------------------------------------------------
extern "C" void kernel_launch(void* const* d_in, const int* in_sizes, int n_in,
                              void* d_out, int out_size)
{
    const float* h     = (const float*)d_in[0];   // [BS, N, F_IN]
    const int*   adj   = (const int*)d_in[1];     // [BS, N, N] bool -> int32
    const float* w     = (const float*)d_in[2];   // [H, F_IN, F_OUT]
    const float* a_src = (const float*)d_in[3];   // [H, F_OUT, 1]
    const float* a_dst = (const float*)d_in[4];   // [H, F_OUT, 1]
    const float* bias  = (const float*)d_in[5];   // [F_OUT]
    float*       out   = (float*)d_out;           // [BS, H, N, F_OUT]

    const dim3 gGemm(NN / 64, FD / 64, BSZ * HH);   // (32, 12, 8)

    // 1) h_prime = h @ w   (per b,h)
    gemm64<false><<<gGemm, 256>>>(h, w, nullptr, nullptr, FD);

    // 2) attn_src / attn_dst from tanh(h_prime)
    attn_vec_kernel<<<BSZ * HH * NN, 256>>>(a_src, a_dst);

    // 3) masked leaky-relu softmax -> P
    softmax_p_kernel<<<BSZ * HH * NN, 256>>>(adj);

    // 4) out = P @ h_prime + bias   (per b,h)
    gemm64<true><<<gGemm, 256>>>(nullptr, nullptr, out, bias, NN);
}

// round 17
// speedup vs baseline: 2.3086x; 2.3086x over previous
#include <cuda_runtime.h>
#include <math.h>
#include <stdint.h>

#define BSZ   4
#define NN    2048
#define HH    2
#define FD    768
#define NEG   0.2f

// GEMM tiling
#define BM 128
#define BN 128
#define BK 32
#define ASTRIDE 36    // 36 % 32 == 4  -> A frag banks = (4g + tig) % 32, conflict-free
#define BSTRIDE 136   // 136 % 32 == 8 -> B frag banks = (8*tig + g) % 32, conflict-free
#define SMEM_FLOATS (2 * (BM * ASTRIDE + BK * BSTRIDE))
#define SMEM_BYTES  (SMEM_FLOATS * 4)   // 71,680 B

// ---------------------------------------------------------------------------
// Device scratch (static — no cudaMalloc allowed)
// ---------------------------------------------------------------------------
__device__ float g_hprime[(size_t)BSZ * HH * NN * FD];   // 50.3 MB
__device__ float g_P     [(size_t)BSZ * HH * NN * NN];   // 134.2 MB
__device__ float g_src   [BSZ * HH * NN];
__device__ float g_dst   [BSZ * HH * NN];

// ---------------------------------------------------------------------------
// PTX helpers
// ---------------------------------------------------------------------------
__device__ __forceinline__ void cp16(uint32_t smem, const void* gmem) {
    asm volatile("cp.async.cg.shared.global [%0], [%1], 16;\n" :: "r"(smem), "l"(gmem));
}
__device__ __forceinline__ void cp_commit() {
    asm volatile("cp.async.commit_group;\n" ::: "memory");
}
template <int N> __device__ __forceinline__ void cp_wait() {
    asm volatile("cp.async.wait_group %0;\n" :: "n"(N) : "memory");
}
__device__ __forceinline__ uint32_t f2tf32(float f) {
    uint32_t r;
    asm("cvt.rna.tf32.f32 %0, %1;\n" : "=r"(r) : "f"(f));
    return r;
}
__device__ __forceinline__ void mma_tf32(float* d, const uint32_t* a, const uint32_t* b) {
    asm volatile(
        "mma.sync.aligned.m16n8k8.row.col.f32.tf32.tf32.f32 "
        "{%0,%1,%2,%3}, {%4,%5,%6,%7}, {%8,%9}, {%0,%1,%2,%3};\n"
        : "+f"(d[0]), "+f"(d[1]), "+f"(d[2]), "+f"(d[3])
        : "r"(a[0]), "r"(a[1]), "r"(a[2]), "r"(a[3]),
          "r"(b[0]), "r"(b[1]));
}

// ---------------------------------------------------------------------------
// tf32 tensor-core GEMM: C[M,N] = A[M,K] @ B[K,N] (+ bias)
// FROM_P=false :  h_prime[bh] = h[b] (2048x768) @ w[hd] (768x768)
// FROM_P=true  :  out[bh]     = P[bh] (2048x2048) @ h_prime[bh] (2048x768) + bias
// Block: 256 threads = 8 warps (4 rows x 2 cols of 32x64 warp tiles).
// ---------------------------------------------------------------------------
template <bool FROM_P>
__global__ __launch_bounds__(256, 1) void gemm_tc(const float* __restrict__ Xg,
                                                  const float* __restrict__ Wg,
                                                  float* __restrict__ Og,
                                                  const float* __restrict__ bias,
                                                  int K)
{
    extern __shared__ float smem[];
    float* As[2] = { smem, smem + BM * ASTRIDE };
    float* Bs[2] = { smem + 2 * BM * ASTRIDE, smem + 2 * BM * ASTRIDE + BK * BSTRIDE };

    const int bh = blockIdx.z;
    const float* A;
    const float* B;
    float*       C;
    int lda;
    if (FROM_P) {
        A = g_P      + (size_t)bh * NN * NN;  lda = NN;
        B = g_hprime + (size_t)bh * NN * FD;
        C = Og       + (size_t)bh * NN * FD;
    } else {
        A = Xg + (size_t)(bh / HH) * NN * FD; lda = FD;
        B = Wg + (size_t)(bh % HH) * FD * FD;
        C = g_hprime + (size_t)bh * NN * FD;
    }
    const int ldb = FD;
    const int m0 = blockIdx.x * BM;
    const int n0 = blockIdx.y * BN;

    const int tid     = threadIdx.x;
    const int warp    = tid >> 5;
    const int lane    = tid & 31;
    const int warpRow = warp & 3;        // 0..3 -> 32-row slab
    const int warpCol = warp >> 2;       // 0..1 -> 64-col slab
    const int g       = lane >> 2;       // group id 0..7
    const int tig     = lane & 3;        // thread-in-group 0..3

    // cp.async load indices (4 x 16B chunks each for A and B per stage)
    const int a_row0 = tid >> 3;              // + 32*i
    const int a_col  = (tid & 7) * 4;
    const int b_row0 = tid >> 5;              // + 8*i
    const int b_col  = (tid & 31) * 4;

    float acc[2][8][4];
#pragma unroll
    for (int mt = 0; mt < 2; mt++)
#pragma unroll
        for (int nt = 0; nt < 8; nt++)
#pragma unroll
            for (int r = 0; r < 4; r++) acc[mt][nt][r] = 0.f;

    const int KT = K / BK;

    // -------- stage loader --------
    auto load_stage = [&](int kt, int buf) {
        const int k0 = kt * BK;
        uint32_t sA = (uint32_t)__cvta_generic_to_shared(As[buf]);
        uint32_t sB = (uint32_t)__cvta_generic_to_shared(Bs[buf]);
#pragma unroll
        for (int i = 0; i < 4; i++) {
            const int r = a_row0 + 32 * i;
            cp16(sA + (uint32_t)(r * ASTRIDE + a_col) * 4,
                 A + (size_t)(m0 + r) * lda + k0 + a_col);
        }
#pragma unroll
        for (int i = 0; i < 4; i++) {
            const int r = b_row0 + 8 * i;
            cp16(sB + (uint32_t)(r * BSTRIDE + b_col) * 4,
                 B + (size_t)(k0 + r) * ldb + n0 + b_col);
        }
    };

    load_stage(0, 0);
    cp_commit();

    for (int kt = 0; kt < KT; kt++) {
        const int cur = kt & 1;
        if (kt + 1 < KT) {
            load_stage(kt + 1, cur ^ 1);
            cp_commit();
            cp_wait<1>();
        } else {
            cp_wait<0>();
        }
        __syncthreads();

        const float* Ac = As[cur];
        const float* Bc = Bs[cur];

#pragma unroll
        for (int ks = 0; ks < BK / 8; ks++) {
            uint32_t a[2][4], b[8][2];
#pragma unroll
            for (int mt = 0; mt < 2; mt++) {
                const int r = warpRow * 32 + mt * 16 + g;
                const int c = ks * 8 + tig;
                a[mt][0] = f2tf32(Ac[r * ASTRIDE + c]);
                a[mt][1] = f2tf32(Ac[(r + 8) * ASTRIDE + c]);
                a[mt][2] = f2tf32(Ac[r * ASTRIDE + c + 4]);
                a[mt][3] = f2tf32(Ac[(r + 8) * ASTRIDE + c + 4]);
            }
#pragma unroll
            for (int nt = 0; nt < 8; nt++) {
                const int col  = warpCol * 64 + nt * 8 + g;
                const int rowk = ks * 8 + tig;
                b[nt][0] = f2tf32(Bc[rowk * BSTRIDE + col]);
                b[nt][1] = f2tf32(Bc[(rowk + 4) * BSTRIDE + col]);
            }
#pragma unroll
            for (int mt = 0; mt < 2; mt++)
#pragma unroll
                for (int nt = 0; nt < 8; nt++)
                    mma_tf32(acc[mt][nt], a[mt], b[nt]);
        }
        __syncthreads();
    }

    // -------- epilogue --------
#pragma unroll
    for (int mt = 0; mt < 2; mt++) {
        const int r = m0 + warpRow * 32 + mt * 16 + g;
#pragma unroll
        for (int nt = 0; nt < 8; nt++) {
            const int cb = n0 + warpCol * 64 + nt * 8 + tig * 2;
            float2 lo = make_float2(acc[mt][nt][0], acc[mt][nt][1]);
            float2 hi = make_float2(acc[mt][nt][2], acc[mt][nt][3]);
            if (FROM_P) {
                lo.x += bias[cb];     lo.y += bias[cb + 1];
                hi.x += bias[cb];     hi.y += bias[cb + 1];
            }
            *reinterpret_cast<float2*>(C + (size_t)r * FD + cb)       = lo;
            *reinterpret_cast<float2*>(C + (size_t)(r + 8) * FD + cb) = hi;
        }
    }
}

// ---------------------------------------------------------------------------
// attn_src / attn_dst : per row, dot(tanh(h_prime_row), a_src[h]) etc.
// ---------------------------------------------------------------------------
__global__ __launch_bounds__(256) void attn_vec_kernel(const float* __restrict__ a_src,
                                                       const float* __restrict__ a_dst)
{
    const int row = blockIdx.x;                 // bh*NN + i
    const int hd  = (row / NN) % HH;
    const float* hp = g_hprime + (size_t)row * FD;

    const int t = threadIdx.x;
    float s = 0.f, d = 0.f;
#pragma unroll
    for (int k = 0; k < FD / 256; k++) {
        const int f = t + k * 256;
        const float v = tanhf(hp[f]);
        s = fmaf(v, a_src[hd * FD + f], s);
        d = fmaf(v, a_dst[hd * FD + f], d);
    }

    __shared__ float rs[256], rd[256];
    rs[t] = s; rd[t] = d;
    __syncthreads();
    for (int off = 128; off > 0; off >>= 1) {
        if (t < off) { rs[t] += rs[t + off]; rd[t] += rd[t + off]; }
        __syncthreads();
    }
    if (t == 0) {
        g_src[row] = rs[0];
        g_dst[row] = rd[0];
    }
}

// ---------------------------------------------------------------------------
// Masked leaky-relu softmax -> P.  adj arrives as int32.
// ---------------------------------------------------------------------------
__global__ __launch_bounds__(256) void softmax_p_kernel(const int* __restrict__ adj)
{
    const int row = blockIdx.x;                 // bh*NN + i
    const int bh  = row / NN;
    const int i   = row % NN;
    const int b   = bh / HH;

    const int* arow = adj + (size_t)b * NN * NN + (size_t)i * NN;
    float* prow = g_P + (size_t)bh * NN * NN + (size_t)i * NN;
    const float srci = g_src[row];
    const float* dstp = g_dst + (size_t)bh * NN;

    __shared__ float sc[NN];
    __shared__ float red[256];

    const int t = threadIdx.x;

    float lmax = -INFINITY;
#pragma unroll
    for (int k = 0; k < NN / 256; k++) {
        const int j = t + k * 256;
        float s = srci + dstp[j];
        s = (s >= 0.f) ? s : NEG * s;           // leaky_relu BEFORE mask
        const bool keep = (arow[j] != 0) || (j == i);
        s = keep ? s : -INFINITY;
        sc[j] = s;
        lmax = fmaxf(lmax, s);
    }

    red[t] = lmax;
    __syncthreads();
    for (int off = 128; off > 0; off >>= 1) {
        if (t < off) red[t] = fmaxf(red[t], red[t + off]);
        __syncthreads();
    }
    const float rowmax = red[0];
    __syncthreads();

    float lsum = 0.f;
#pragma unroll
    for (int k = 0; k < NN / 256; k++) {
        const int j = t + k * 256;
        const float e = expf(sc[j] - rowmax);
        sc[j] = e;
        lsum += e;
    }
    red[t] = lsum;
    __syncthreads();
    for (int off = 128; off > 0; off >>= 1) {
        if (t < off) red[t] += red[t + off];
        __syncthreads();
    }
    const float inv = 1.f / red[0];
    __syncthreads();

#pragma unroll
    for (int k = 0; k < NN / 256; k++) {
        const int j = t + k * 256;
        prow[j] = sc[j] * inv;
    }
}

// ---------------------------------------------------------------------------
// Launch
// ---------------------------------------------------------------------------
extern "C" void kernel_launch(void* const* d_in, const int* in_sizes, int n_in,
                              void* d_out, int out_size)
{
    const float* h     = (const float*)d_in[0];   // [BS, N, F_IN]
    const int*   adj   = (const int*)d_in[1];     // [BS, N, N] bool -> int32
    const float* w     = (const float*)d_in[2];   // [H, F_IN, F_OUT]
    const float* a_src = (const float*)d_in[3];   // [H, F_OUT, 1]
    const float* a_dst = (const float*)d_in[4];   // [H, F_OUT, 1]
    const float* bias  = (const float*)d_in[5];   // [F_OUT]
    float*       out   = (float*)d_out;           // [BS, H, N, F_OUT]

    static bool attr_done = false;
    if (!attr_done) {
        cudaFuncSetAttribute(gemm_tc<false>,
                             cudaFuncAttributeMaxDynamicSharedMemorySize, SMEM_BYTES);
        cudaFuncSetAttribute(gemm_tc<true>,
                             cudaFuncAttributeMaxDynamicSharedMemorySize, SMEM_BYTES);
        attr_done = true;
    }

    const dim3 gGemm(NN / BM, FD / BN, BSZ * HH);   // (16, 6, 8)

    // 1) h_prime = h @ w
    gemm_tc<false><<<gGemm, 256, SMEM_BYTES>>>(h, w, nullptr, nullptr, FD);

    // 2) attn_src / attn_dst from tanh(h_prime)
    attn_vec_kernel<<<BSZ * HH * NN, 256>>>(a_src, a_dst);

    // 3) masked leaky-relu softmax -> P
    softmax_p_kernel<<<BSZ * HH * NN, 256>>>(adj);

    // 4) out = P @ h_prime + bias
    gemm_tc<true><<<gGemm, 256, SMEM_BYTES>>>(nullptr, nullptr, out, bias, NN);
}